// round 2
// baseline (speedup 1.0000x reference)
#include <cuda_runtime.h>

#define NN 100000
#define NE 1600000
#define NF 64
#define NC 32

// ---------------- scratch (static device memory; no runtime allocation) ----
__device__ float g_bufA[NN * NF];   // prescaled features / layer outputs
__device__ float g_bufB[NN * NF];   // aggregation results
__device__ float g_bufC[NN * NC];   // layer-3 transformed features (width 32)
__device__ int   g_deg_out[NN];
__device__ int   g_deg_in[NN];
__device__ float g_norm_out[NN];
__device__ float g_norm_in[NN];
__device__ int   g_row_ptr[NN + 1];
__device__ int   g_cursor[NN];
__device__ int   g_partials[64];
__device__ int   g_edge_src[NE];

// ---------------- degree histograms --------------------------------------
__global__ void k_zero() {
    int i = blockIdx.x * blockDim.x + threadIdx.x;
    if (i < NN) { g_deg_out[i] = 0; g_deg_in[i] = 0; }
}

__global__ void k_hist(const int* __restrict__ src, const int* __restrict__ dst) {
    int i = blockIdx.x * blockDim.x + threadIdx.x;
    if (i < NE) {
        atomicAdd(&g_deg_out[src[i]], 1);
        atomicAdd(&g_deg_in[dst[i]], 1);
    }
}

__global__ void k_norm() {
    int i = blockIdx.x * blockDim.x + threadIdx.x;
    if (i < NN) {
        g_norm_out[i] = rsqrtf((float)max(g_deg_out[i], 1));
        g_norm_in[i]  = rsqrtf((float)max(g_deg_in[i], 1));
    }
}

// ---------------- exclusive scan of in-degrees (row_ptr) ------------------
#define SCAN_T 512
#define SCAN_I 4
#define SCAN_CHUNK (SCAN_T * SCAN_I)                     // 2048
#define SCAN_NB ((NN + SCAN_CHUNK - 1) / SCAN_CHUNK)     // 49

__global__ void k_scan1() {
    __shared__ int sm[SCAN_T];
    int tid = threadIdx.x;
    int base = blockIdx.x * SCAN_CHUNK + tid * SCAN_I;
    int s = 0;
#pragma unroll
    for (int j = 0; j < SCAN_I; j++) {
        int i = base + j;
        if (i < NN) s += g_deg_in[i];
    }
    sm[tid] = s;
    __syncthreads();
    for (int off = SCAN_T / 2; off > 0; off >>= 1) {
        if (tid < off) sm[tid] += sm[tid + off];
        __syncthreads();
    }
    if (tid == 0) g_partials[blockIdx.x] = sm[0];
}

__global__ void k_scan2() {
    if (threadIdx.x == 0 && blockIdx.x == 0) {
        int run = 0;
        for (int b = 0; b < SCAN_NB; b++) {
            int v = g_partials[b];
            g_partials[b] = run;
            run += v;
        }
        g_row_ptr[NN] = run;   // == NE
    }
}

__global__ void k_scan3() {
    __shared__ int sm[SCAN_T];
    int tid = threadIdx.x;
    int base = blockIdx.x * SCAN_CHUNK + tid * SCAN_I;
    int c[SCAN_I];
    int s = 0;
#pragma unroll
    for (int j = 0; j < SCAN_I; j++) {
        int i = base + j;
        c[j] = (i < NN) ? g_deg_in[i] : 0;
        s += c[j];
    }
    sm[tid] = s;
    __syncthreads();
    // Hillis-Steele inclusive scan
    for (int off = 1; off < SCAN_T; off <<= 1) {
        int v = (tid >= off) ? sm[tid - off] : 0;
        __syncthreads();
        sm[tid] += v;
        __syncthreads();
    }
    int excl = sm[tid] - s + g_partials[blockIdx.x];
#pragma unroll
    for (int j = 0; j < SCAN_I; j++) {
        int i = base + j;
        if (i < NN) { g_row_ptr[i] = excl; g_cursor[i] = excl; }
        excl += c[j];
    }
}

__global__ void k_scatter(const int* __restrict__ src, const int* __restrict__ dst) {
    int i = blockIdx.x * blockDim.x + threadIdx.x;
    if (i < NE) {
        int d = dst[i];
        int pos = atomicAdd(&g_cursor[d], 1);
        g_edge_src[pos] = src[i];
    }
}

// ---------------- feature prescale: bufA = x * norm_out[row] --------------
__global__ void k_prescale(const float* __restrict__ x) {
    int i = blockIdx.x * blockDim.x + threadIdx.x;   // over NN*NF/2 float2
    if (i < NN * NF / 2) {
        int row = i / (NF / 2);
        float2 v = ((const float2*)x)[i];
        float s = g_norm_out[row];
        v.x *= s; v.y *= s;
        ((float2*)g_bufA)[i] = v;
    }
}

// ---------------- CSR aggregation, width 64 (warp per dst node) -----------
__global__ void k_agg64(const float* __restrict__ in, float* __restrict__ out) {
    int w = (blockIdx.x * blockDim.x + threadIdx.x) >> 5;
    int lane = threadIdx.x & 31;
    if (w >= NN) return;
    int beg = g_row_ptr[w], end = g_row_ptr[w + 1];
    float ax = 0.f, ay = 0.f;
    int e = beg;
    for (; e + 1 < end; e += 2) {
        int s0 = g_edge_src[e];
        int s1 = g_edge_src[e + 1];
        float2 v0 = *(const float2*)&in[s0 * NF + lane * 2];
        float2 v1 = *(const float2*)&in[s1 * NF + lane * 2];
        ax += v0.x + v1.x;
        ay += v0.y + v1.y;
    }
    if (e < end) {
        int s0 = g_edge_src[e];
        float2 v0 = *(const float2*)&in[s0 * NF + lane * 2];
        ax += v0.x; ay += v0.y;
    }
    float2 o; o.x = ax; o.y = ay;
    *(float2*)&out[w * NF + lane * 2] = o;
}

// ---------------- CSR aggregation, width 32, fused norm_in + bias → out ---
__global__ void k_agg32(const float* __restrict__ in, const float* __restrict__ b3,
                        float* __restrict__ out) {
    int w = (blockIdx.x * blockDim.x + threadIdx.x) >> 5;
    int lane = threadIdx.x & 31;
    if (w >= NN) return;
    int beg = g_row_ptr[w], end = g_row_ptr[w + 1];
    float a = 0.f;
    int e = beg;
    for (; e + 1 < end; e += 2) {
        int s0 = g_edge_src[e];
        int s1 = g_edge_src[e + 1];
        a += in[s0 * NC + lane] + in[s1 * NC + lane];
    }
    if (e < end) a += in[g_edge_src[e] * NC + lane];
    out[w * NC + lane] = a * g_norm_in[w] + b3[lane];
}

// ---------------- tiled GEMM: out = epi((in * norm_in?) @ W + b?) ---------
// Block tile: BR rows x NCOL cols, 256 threads, thread tile 2x4.
template <int NCOL, bool PRE, bool BIAS, bool RELU, bool POST>
__global__ void k_gemm(const float* __restrict__ in, const float* __restrict__ W,
                       const float* __restrict__ b, float* __restrict__ out) {
    constexpr int BR = 2048 / NCOL;     // 32 for NCOL=64, 64 for NCOL=32
    constexpr int ISTR = NF + 4;        // padded row stride (bank-conflict free)
    __shared__ __align__(16) float Ws[NF * NCOL];
    __shared__ float Is[BR][ISTR];

    int tid = threadIdx.x;
    int row0 = blockIdx.x * BR;

    // load W (row-major [NF][NCOL]) into smem
    for (int i = tid; i < NF * NCOL; i += 256) Ws[i] = W[i];

    // load input tile, optionally pre-scaled by norm_in[row]
    for (int i = tid; i < BR * NF; i += 256) {
        int r = i / NF, k = i % NF;
        int g = row0 + r;
        float v = 0.f;
        if (g < NN) {
            v = in[g * NF + k];
            if (PRE) v *= g_norm_in[g];
        }
        Is[r][k] = v;
    }
    __syncthreads();

    int tcol = (tid % (NCOL / 4)) * 4;
    int trow = (tid / (NCOL / 4)) * 2;

    float acc[2][4] = {};
#pragma unroll
    for (int k = 0; k < NF; k++) {
        float4 w = *(const float4*)&Ws[k * NCOL + tcol];
        float a0 = Is[trow][k];
        float a1 = Is[trow + 1][k];
        acc[0][0] += a0 * w.x; acc[0][1] += a0 * w.y;
        acc[0][2] += a0 * w.z; acc[0][3] += a0 * w.w;
        acc[1][0] += a1 * w.x; acc[1][1] += a1 * w.y;
        acc[1][2] += a1 * w.z; acc[1][3] += a1 * w.w;
    }

    float4 bb = make_float4(0.f, 0.f, 0.f, 0.f);
    if (BIAS) bb = *(const float4*)&b[tcol];

#pragma unroll
    for (int rr = 0; rr < 2; rr++) {
        int g = row0 + trow + rr;
        if (g < NN) {
            float4 o;
            o.x = acc[rr][0] + bb.x;
            o.y = acc[rr][1] + bb.y;
            o.z = acc[rr][2] + bb.z;
            o.w = acc[rr][3] + bb.w;
            if (RELU) {
                o.x = fmaxf(o.x, 0.f); o.y = fmaxf(o.y, 0.f);
                o.z = fmaxf(o.z, 0.f); o.w = fmaxf(o.w, 0.f);
            }
            if (POST) {
                float s = g_norm_out[g];
                o.x *= s; o.y *= s; o.z *= s; o.w *= s;
            }
            *(float4*)&out[g * NCOL + tcol] = o;
        }
    }
}

// ---------------- launch -------------------------------------------------
extern "C" void kernel_launch(void* const* d_in, const int* in_sizes, int n_in,
                              void* d_out, int out_size) {
    const float* x   = (const float*)d_in[0];
    const int*   src = (const int*)d_in[1];
    const int*   dst = (const int*)d_in[2];
    const float* W1  = (const float*)d_in[3];
    const float* b1  = (const float*)d_in[4];
    const float* W2  = (const float*)d_in[5];
    const float* b2  = (const float*)d_in[6];
    const float* W3  = (const float*)d_in[7];
    const float* b3  = (const float*)d_in[8];
    float* out = (float*)d_out;

    float *pA, *pB, *pC;
    cudaGetSymbolAddress((void**)&pA, g_bufA);
    cudaGetSymbolAddress((void**)&pB, g_bufB);
    cudaGetSymbolAddress((void**)&pC, g_bufC);

    const int NB_NODE = (NN + 255) / 256;          // 391
    const int NB_EDGE = (NE + 255) / 256;          // 6250
    const int NB_WARP = (NN * 32 + 255) / 256;     // 12500
    const int NB_PRE  = (NN * NF / 2 + 255) / 256; // 12500

    // graph preprocessing (per launch; inputs fixed)
    k_zero<<<NB_NODE, 256>>>();
    k_hist<<<NB_EDGE, 256>>>(src, dst);
    k_norm<<<NB_NODE, 256>>>();
    k_scan1<<<SCAN_NB, SCAN_T>>>();
    k_scan2<<<1, 32>>>();
    k_scan3<<<SCAN_NB, SCAN_T>>>();
    k_scatter<<<NB_EDGE, 256>>>(src, dst);

    // layer 1
    k_prescale<<<NB_PRE, 256>>>(x);
    k_agg64<<<NB_WARP, 256>>>(pA, pB);
    k_gemm<64, true, true, true, true><<<(NN + 31) / 32, 256>>>(pB, W1, b1, pA);

    // layer 2
    k_agg64<<<NB_WARP, 256>>>(pA, pB);
    k_gemm<64, true, true, true, true><<<(NN + 31) / 32, 256>>>(pB, W2, b2, pA);

    // layer 3: transform-before-aggregate (width 32), then fused agg+norm+bias
    k_gemm<32, false, false, false, false><<<(NN + 63) / 64, 256>>>(pA, W3, nullptr, pC);
    k_agg32<<<NB_WARP, 256>>>(pC, b3, out);
}

// round 4
// speedup vs baseline: 1.0092x; 1.0092x over previous
#include <cuda_runtime.h>
#include <cuda_fp16.h>

#define NN 100000
#define NE 1600000
#define NF 64
#define NC 32

// ---------------- scratch (static device memory) --------------------------
__device__ __half2 g_x16[NN * (NF / 2)];   // prescaled x (fp16)
__device__ __half2 g_h1[NN * (NF / 2)];    // layer-1 output (fp16)
__device__ __half2 g_t3[NN * (NC / 2)];    // W3-transformed h2 (fp16)
__device__ int   g_deg_out[NN];            // zero-init; re-zeroed each launch tail
__device__ int   g_deg_in[NN];
__device__ float g_norm_out[NN];
__device__ float g_norm_in[NN];
__device__ int   g_row_ptr[NN + 1];
__device__ int   g_cursor[NN];
__device__ int   g_partials[64];
__device__ int   g_edge_src[NE];

// ---------------- degree histograms --------------------------------------
__global__ void k_hist(const int* __restrict__ src, const int* __restrict__ dst) {
    int i = blockIdx.x * blockDim.x + threadIdx.x;
    if (i < NE) {
        atomicAdd(&g_deg_out[src[i]], 1);
        atomicAdd(&g_deg_in[dst[i]], 1);
    }
}

// ---------------- scan pass 1 (+ fused norm computation) ------------------
#define SCAN_T 512
#define SCAN_I 4
#define SCAN_CHUNK (SCAN_T * SCAN_I)                     // 2048
#define SCAN_NB ((NN + SCAN_CHUNK - 1) / SCAN_CHUNK)     // 49

__global__ void k_scan1() {
    __shared__ int sm[SCAN_T];
    int tid = threadIdx.x;
    int base = blockIdx.x * SCAN_CHUNK + tid * SCAN_I;
    int s = 0;
#pragma unroll
    for (int j = 0; j < SCAN_I; j++) {
        int i = base + j;
        if (i < NN) {
            int di = g_deg_in[i];
            s += di;
            g_norm_in[i]  = rsqrtf((float)max(di, 1));
            g_norm_out[i] = rsqrtf((float)max(g_deg_out[i], 1));
        }
    }
    sm[tid] = s;
    __syncthreads();
    for (int off = SCAN_T / 2; off > 0; off >>= 1) {
        if (tid < off) sm[tid] += sm[tid + off];
        __syncthreads();
    }
    if (tid == 0) g_partials[blockIdx.x] = sm[0];
}

__global__ void k_scan2() {
    if (threadIdx.x == 0 && blockIdx.x == 0) {
        int run = 0;
        for (int b = 0; b < SCAN_NB; b++) {
            int v = g_partials[b];
            g_partials[b] = run;
            run += v;
        }
        g_row_ptr[NN] = run;
    }
}

__global__ void k_scan3() {
    __shared__ int sm[SCAN_T];
    int tid = threadIdx.x;
    int base = blockIdx.x * SCAN_CHUNK + tid * SCAN_I;
    int c[SCAN_I];
    int s = 0;
#pragma unroll
    for (int j = 0; j < SCAN_I; j++) {
        int i = base + j;
        c[j] = (i < NN) ? g_deg_in[i] : 0;
        s += c[j];
    }
    sm[tid] = s;
    __syncthreads();
    for (int off = 1; off < SCAN_T; off <<= 1) {
        int v = (tid >= off) ? sm[tid - off] : 0;
        __syncthreads();
        sm[tid] += v;
        __syncthreads();
    }
    int excl = sm[tid] - s + g_partials[blockIdx.x];
#pragma unroll
    for (int j = 0; j < SCAN_I; j++) {
        int i = base + j;
        if (i < NN) { g_row_ptr[i] = excl; g_cursor[i] = excl; }
        excl += c[j];
    }
}

__global__ void k_scatter(const int* __restrict__ src, const int* __restrict__ dst) {
    int i = blockIdx.x * blockDim.x + threadIdx.x;
    if (i < NE) {
        int d = dst[i];
        int pos = atomicAdd(&g_cursor[d], 1);
        g_edge_src[pos] = src[i];
    }
}

// ---------------- prescale: g_x16 = fp16(x * norm_out[row]) ---------------
__global__ void k_prescale(const float* __restrict__ x) {
    int i = blockIdx.x * blockDim.x + threadIdx.x;   // over NN*32 half2
    if (i < NN * (NF / 2)) {
        int row = i >> 5;
        float2 v = ((const float2*)x)[i];
        float s = g_norm_out[row];
        g_x16[i] = __floats2half2_rn(v.x * s, v.y * s);
    }
}

// ---------------- fused layer: agg(fp16) + norm_in + GEMM + epi -----------
// 256 threads, 32 nodes/block, grid = 3125 (exact: 3125*32 = 100000).
__global__ __launch_bounds__(256) void k_layer1(const float* __restrict__ W1,
                                                const float* __restrict__ b1) {
    __shared__ __align__(16) float Ws[NF * NF];
    __shared__ float Is[32][NF + 2];
    int tid = threadIdx.x;
    int row0 = blockIdx.x * 32;
    for (int i = tid; i < NF * NF; i += 256) Ws[i] = W1[i];

    int wid = tid >> 5, lane = tid & 31;
#pragma unroll
    for (int j = 0; j < 4; j++) {
        int nl = (wid << 2) + j;
        int node = row0 + nl;
        int beg = g_row_ptr[node], end = g_row_ptr[node + 1];
        float ax = 0.f, ay = 0.f;
        int e = beg;
        for (; e + 3 < end; e += 4) {
            int s0 = g_edge_src[e], s1 = g_edge_src[e + 1];
            int s2 = g_edge_src[e + 2], s3 = g_edge_src[e + 3];
            float2 v0 = __half22float2(g_x16[s0 * 32 + lane]);
            float2 v1 = __half22float2(g_x16[s1 * 32 + lane]);
            float2 v2 = __half22float2(g_x16[s2 * 32 + lane]);
            float2 v3 = __half22float2(g_x16[s3 * 32 + lane]);
            ax += (v0.x + v1.x) + (v2.x + v3.x);
            ay += (v0.y + v1.y) + (v2.y + v3.y);
        }
        for (; e < end; e++) {
            float2 v = __half22float2(g_x16[g_edge_src[e] * 32 + lane]);
            ax += v.x; ay += v.y;
        }
        float ni = g_norm_in[node];
        Is[nl][lane * 2]     = ax * ni;
        Is[nl][lane * 2 + 1] = ay * ni;
    }
    __syncthreads();

    int tcol = (tid & 15) * 4;
    int trow = (tid >> 4) * 2;
    float acc[2][4] = {};
#pragma unroll
    for (int k = 0; k < NF; k++) {
        float4 w = *(const float4*)&Ws[k * NF + tcol];
        float a0 = Is[trow][k], a1 = Is[trow + 1][k];
        acc[0][0] += a0 * w.x; acc[0][1] += a0 * w.y;
        acc[0][2] += a0 * w.z; acc[0][3] += a0 * w.w;
        acc[1][0] += a1 * w.x; acc[1][1] += a1 * w.y;
        acc[1][2] += a1 * w.z; acc[1][3] += a1 * w.w;
    }
    float4 bb = *(const float4*)&b1[tcol];
#pragma unroll
    for (int rr = 0; rr < 2; rr++) {
        int g = row0 + trow + rr;
        float so = g_norm_out[g];
        float o0 = fmaxf(acc[rr][0] + bb.x, 0.f) * so;
        float o1 = fmaxf(acc[rr][1] + bb.y, 0.f) * so;
        float o2 = fmaxf(acc[rr][2] + bb.z, 0.f) * so;
        float o3 = fmaxf(acc[rr][3] + bb.w, 0.f) * so;
        g_h1[g * 32 + (tcol >> 1)]     = __floats2half2_rn(o0, o1);
        g_h1[g * 32 + (tcol >> 1) + 1] = __floats2half2_rn(o2, o3);
    }
}

// layer 2 + fused W3 transform: t3 = (relu(aggW2+b2)*norm_out) @ W3  (fp16 out)
__global__ __launch_bounds__(256) void k_layer2(const float* __restrict__ W2,
                                                const float* __restrict__ b2,
                                                const float* __restrict__ W3) {
    __shared__ __align__(16) float Ws[NF * NF];
    __shared__ __align__(16) float W3s[NF * NC];
    __shared__ float Is[32][NF + 2];
    int tid = threadIdx.x;
    int row0 = blockIdx.x * 32;
    for (int i = tid; i < NF * NF; i += 256) Ws[i] = W2[i];
    for (int i = tid; i < NF * NC; i += 256) W3s[i] = W3[i];

    int wid = tid >> 5, lane = tid & 31;
#pragma unroll
    for (int j = 0; j < 4; j++) {
        int nl = (wid << 2) + j;
        int node = row0 + nl;
        int beg = g_row_ptr[node], end = g_row_ptr[node + 1];
        float ax = 0.f, ay = 0.f;
        int e = beg;
        for (; e + 3 < end; e += 4) {
            int s0 = g_edge_src[e], s1 = g_edge_src[e + 1];
            int s2 = g_edge_src[e + 2], s3 = g_edge_src[e + 3];
            float2 v0 = __half22float2(g_h1[s0 * 32 + lane]);
            float2 v1 = __half22float2(g_h1[s1 * 32 + lane]);
            float2 v2 = __half22float2(g_h1[s2 * 32 + lane]);
            float2 v3 = __half22float2(g_h1[s3 * 32 + lane]);
            ax += (v0.x + v1.x) + (v2.x + v3.x);
            ay += (v0.y + v1.y) + (v2.y + v3.y);
        }
        for (; e < end; e++) {
            float2 v = __half22float2(g_h1[g_edge_src[e] * 32 + lane]);
            ax += v.x; ay += v.y;
        }
        float ni = g_norm_in[node];
        Is[nl][lane * 2]     = ax * ni;
        Is[nl][lane * 2 + 1] = ay * ni;
    }
    __syncthreads();

    int tcol = (tid & 15) * 4;
    int trow = (tid >> 4) * 2;
    float acc[2][4] = {};
#pragma unroll
    for (int k = 0; k < NF; k++) {
        float4 w = *(const float4*)&Ws[k * NF + tcol];
        float a0 = Is[trow][k], a1 = Is[trow + 1][k];
        acc[0][0] += a0 * w.x; acc[0][1] += a0 * w.y;
        acc[0][2] += a0 * w.z; acc[0][3] += a0 * w.w;
        acc[1][0] += a1 * w.x; acc[1][1] += a1 * w.y;
        acc[1][2] += a1 * w.z; acc[1][3] += a1 * w.w;
    }
    float4 bb = *(const float4*)&b2[tcol];
    float h2v[2][4];
#pragma unroll
    for (int rr = 0; rr < 2; rr++) {
        float so = g_norm_out[row0 + trow + rr];
        h2v[rr][0] = fmaxf(acc[rr][0] + bb.x, 0.f) * so;
        h2v[rr][1] = fmaxf(acc[rr][1] + bb.y, 0.f) * so;
        h2v[rr][2] = fmaxf(acc[rr][2] + bb.z, 0.f) * so;
        h2v[rr][3] = fmaxf(acc[rr][3] + bb.w, 0.f) * so;
    }
    __syncthreads();   // all reads of Is done before overwrite
#pragma unroll
    for (int rr = 0; rr < 2; rr++) {
        Is[trow + rr][tcol]     = h2v[rr][0];
        Is[trow + rr][tcol + 1] = h2v[rr][1];
        Is[trow + rr][tcol + 2] = h2v[rr][2];
        Is[trow + rr][tcol + 3] = h2v[rr][3];
    }
    __syncthreads();

    // phase 3: t3 = h2n @ W3  (32x32 tile, 1x4 per thread)
    int trow2 = tid >> 3;
    int tcol2 = (tid & 7) * 4;
    float a4[4] = {};
#pragma unroll
    for (int k = 0; k < NF; k++) {
        float h = Is[trow2][k];
        float4 w = *(const float4*)&W3s[k * NC + tcol2];
        a4[0] += h * w.x; a4[1] += h * w.y;
        a4[2] += h * w.z; a4[3] += h * w.w;
    }
    int g = row0 + trow2;
    g_t3[g * 16 + (tcol2 >> 1)]     = __floats2half2_rn(a4[0], a4[1]);
    g_t3[g * 16 + (tcol2 >> 1) + 1] = __floats2half2_rn(a4[2], a4[3]);
}

// ---------------- final: out = norm_in * Agg(t3) + b3 (+ deg re-zero) -----
// grid = NN*32/256 = 12500 blocks: one warp per node, lane = output column.
__global__ void k_out(const float* __restrict__ b3, float* __restrict__ out) {
    int gt = blockIdx.x * blockDim.x + threadIdx.x;
    int w = gt >> 5, lane = gt & 31;
    const __half* t3 = (const __half*)g_t3;
    int beg = g_row_ptr[w], end = g_row_ptr[w + 1];
    float a = 0.f;
    int e = beg;
    for (; e + 3 < end; e += 4) {
        int s0 = g_edge_src[e], s1 = g_edge_src[e + 1];
        int s2 = g_edge_src[e + 2], s3 = g_edge_src[e + 3];
        a += (__half2float(t3[s0 * 32 + lane]) + __half2float(t3[s1 * 32 + lane]))
           + (__half2float(t3[s2 * 32 + lane]) + __half2float(t3[s3 * 32 + lane]));
    }
    for (; e < end; e++) a += __half2float(t3[g_edge_src[e] * 32 + lane]);
    out[w * 32 + lane] = a * g_norm_in[w] + b3[lane];
    // restore zeroed degree state for next replay
    if (gt < NN) { g_deg_out[gt] = 0; g_deg_in[gt] = 0; }
}

// ---------------- launch -------------------------------------------------
extern "C" void kernel_launch(void* const* d_in, const int* in_sizes, int n_in,
                              void* d_out, int out_size) {
    const float* x   = (const float*)d_in[0];
    const int*   src = (const int*)d_in[1];
    const int*   dst = (const int*)d_in[2];
    const float* W1  = (const float*)d_in[3];
    const float* b1  = (const float*)d_in[4];
    const float* W2  = (const float*)d_in[5];
    const float* b2  = (const float*)d_in[6];
    const float* W3  = (const float*)d_in[7];
    const float* b3  = (const float*)d_in[8];
    float* out = (float*)d_out;

    const int NB_EDGE = (NE + 255) / 256;               // 6250
    const int NB_PRE  = (NN * (NF / 2) + 255) / 256;    // 12500
    const int NB_OUT  = NN * 32 / 256;                  // 12500  (FIXED)

    k_hist<<<NB_EDGE, 256>>>(src, dst);
    k_scan1<<<SCAN_NB, SCAN_T>>>();
    k_scan2<<<1, 32>>>();
    k_scan3<<<SCAN_NB, SCAN_T>>>();
    k_scatter<<<NB_EDGE, 256>>>(src, dst);
    k_prescale<<<NB_PRE, 256>>>(x);
    k_layer1<<<NN / 32, 256>>>(W1, b1);
    k_layer2<<<NN / 32, 256>>>(W2, b2, W3);
    k_out<<<NB_OUT, 256>>>(b3, out);
}

// round 5
// speedup vs baseline: 1.1963x; 1.1854x over previous
#include <cuda_runtime.h>
#include <cuda_fp16.h>

#define NN 100000
#define NE 1600000
#define NF 64
#define NC 32

// ---------------- scratch (static device memory) --------------------------
__device__ __align__(256) __half2 g_x16[NN * (NF / 2)];   // prescaled x (fp16)
__device__ __align__(256) __half2 g_h1[NN * (NF / 2)];    // layer-1 output (fp16)
__device__ __align__(256) __half2 g_t3[NN * (NC / 2)];    // W3-transformed h2 (fp16)
__device__ int   g_deg_out[NN];            // zero-init; re-zeroed each launch tail
__device__ int   g_deg_in[NN];
__device__ float g_norm_out[NN];
__device__ float g_norm_in[NN];
__device__ int   g_row_ptr[NN + 1];
__device__ int   g_cursor[NN];
__device__ int   g_partials[64];
__device__ __align__(256) int g_edge_src[NE];

// ---------------- degree histograms (int4: 4 edges/thread) ----------------
__global__ void k_hist(const int4* __restrict__ src4, const int4* __restrict__ dst4) {
    int i = blockIdx.x * blockDim.x + threadIdx.x;
    if (i < NE / 4) {
        int4 s = src4[i];
        int4 d = dst4[i];
        atomicAdd(&g_deg_out[s.x], 1); atomicAdd(&g_deg_out[s.y], 1);
        atomicAdd(&g_deg_out[s.z], 1); atomicAdd(&g_deg_out[s.w], 1);
        atomicAdd(&g_deg_in[d.x], 1);  atomicAdd(&g_deg_in[d.y], 1);
        atomicAdd(&g_deg_in[d.z], 1);  atomicAdd(&g_deg_in[d.w], 1);
    }
}

// ---------------- scan pass 1 (+ fused norm computation) ------------------
#define SCAN_T 512
#define SCAN_I 4
#define SCAN_CHUNK (SCAN_T * SCAN_I)                     // 2048
#define SCAN_NB ((NN + SCAN_CHUNK - 1) / SCAN_CHUNK)     // 49

__global__ void k_scan1() {
    __shared__ int sm[SCAN_T];
    int tid = threadIdx.x;
    int base = blockIdx.x * SCAN_CHUNK + tid * SCAN_I;
    int s = 0;
#pragma unroll
    for (int j = 0; j < SCAN_I; j++) {
        int i = base + j;
        if (i < NN) {
            int di = g_deg_in[i];
            s += di;
            g_norm_in[i]  = rsqrtf((float)max(di, 1));
            g_norm_out[i] = rsqrtf((float)max(g_deg_out[i], 1));
        }
    }
    sm[tid] = s;
    __syncthreads();
    for (int off = SCAN_T / 2; off > 0; off >>= 1) {
        if (tid < off) sm[tid] += sm[tid + off];
        __syncthreads();
    }
    if (tid == 0) g_partials[blockIdx.x] = sm[0];
}

__global__ void k_scan2() {
    if (threadIdx.x == 0 && blockIdx.x == 0) {
        int run = 0;
        for (int b = 0; b < SCAN_NB; b++) {
            int v = g_partials[b];
            g_partials[b] = run;
            run += v;
        }
        g_row_ptr[NN] = run;
    }
}

__global__ void k_scan3() {
    __shared__ int sm[SCAN_T];
    int tid = threadIdx.x;
    int base = blockIdx.x * SCAN_CHUNK + tid * SCAN_I;
    int c[SCAN_I];
    int s = 0;
#pragma unroll
    for (int j = 0; j < SCAN_I; j++) {
        int i = base + j;
        c[j] = (i < NN) ? g_deg_in[i] : 0;
        s += c[j];
    }
    sm[tid] = s;
    __syncthreads();
    for (int off = 1; off < SCAN_T; off <<= 1) {
        int v = (tid >= off) ? sm[tid - off] : 0;
        __syncthreads();
        sm[tid] += v;
        __syncthreads();
    }
    int excl = sm[tid] - s + g_partials[blockIdx.x];
#pragma unroll
    for (int j = 0; j < SCAN_I; j++) {
        int i = base + j;
        if (i < NN) { g_row_ptr[i] = excl; g_cursor[i] = excl; }
        excl += c[j];
    }
}

__global__ void k_scatter(const int4* __restrict__ src4, const int4* __restrict__ dst4) {
    int i = blockIdx.x * blockDim.x + threadIdx.x;
    if (i < NE / 4) {
        int4 s = src4[i];
        int4 d = dst4[i];
        g_edge_src[atomicAdd(&g_cursor[d.x], 1)] = s.x;
        g_edge_src[atomicAdd(&g_cursor[d.y], 1)] = s.y;
        g_edge_src[atomicAdd(&g_cursor[d.z], 1)] = s.z;
        g_edge_src[atomicAdd(&g_cursor[d.w], 1)] = s.w;
    }
}

// ---------------- prescale: g_x16 = fp16(x * norm_out[row]) ---------------
__global__ void k_prescale(const float* __restrict__ x) {
    int i = blockIdx.x * blockDim.x + threadIdx.x;   // over NN*16 float4
    if (i < NN * (NF / 4)) {
        int row = i >> 4;
        float4 v = ((const float4*)x)[i];
        float s = g_norm_out[row];
        g_x16[i * 2]     = __floats2half2_rn(v.x * s, v.y * s);
        g_x16[i * 2 + 1] = __floats2half2_rn(v.z * s, v.w * s);
    }
}

// ---------------- vectorized gather-aggregate (4 edges per warp-LDG) ------
// Each lane loads 16B (8 halves): 8 lanes per edge row, edge slot = lane>>3,
// feature chunk = (lane&7)*8. Cross-slot reduce via shfl_xor(8|16).
__device__ __forceinline__ void agg64_node(const __half* __restrict__ inh,
                                           int beg, int end, int sub, int fc,
                                           float acc[8]) {
#pragma unroll
    for (int q = 0; q < 8; q++) acc[q] = 0.f;
    for (int e = beg; e < end; e += 4) {
        int eid = e + sub;
        uint4 v = make_uint4(0u, 0u, 0u, 0u);
        if (eid < end) {
            int s = g_edge_src[eid];
            v = *(const uint4*)&inh[s * NF + fc];
        }
        float2 f0 = __half22float2(*(const __half2*)&v.x);
        float2 f1 = __half22float2(*(const __half2*)&v.y);
        float2 f2 = __half22float2(*(const __half2*)&v.z);
        float2 f3 = __half22float2(*(const __half2*)&v.w);
        acc[0] += f0.x; acc[1] += f0.y; acc[2] += f1.x; acc[3] += f1.y;
        acc[4] += f2.x; acc[5] += f2.y; acc[6] += f3.x; acc[7] += f3.y;
    }
#pragma unroll
    for (int q = 0; q < 8; q++) {
        acc[q] += __shfl_xor_sync(0xffffffffu, acc[q], 8);
        acc[q] += __shfl_xor_sync(0xffffffffu, acc[q], 16);
    }
}

// ---------------- fused layer 1: agg + norm_in + GEMM + relu + norm_out ---
__global__ __launch_bounds__(256) void k_layer1(const float* __restrict__ W1,
                                                const float* __restrict__ b1) {
    __shared__ __align__(16) float Ws[NF * NF];
    __shared__ float Is[32][NF + 2];
    int tid = threadIdx.x;
    int row0 = blockIdx.x * 32;
    for (int i = tid; i < NF * NF; i += 256) Ws[i] = W1[i];

    const __half* inh = (const __half*)g_x16;
    int wid = tid >> 5, lane = tid & 31;
    int sub = lane >> 3;
    int fc  = (lane & 7) * 8;
#pragma unroll
    for (int j = 0; j < 4; j++) {
        int nl = (wid << 2) + j;
        int node = row0 + nl;
        float acc[8];
        agg64_node(inh, g_row_ptr[node], g_row_ptr[node + 1], sub, fc, acc);
        if (lane < 8) {
            float ni = g_norm_in[node];
#pragma unroll
            for (int q = 0; q < 8; q++) Is[nl][fc + q] = acc[q] * ni;
        }
    }
    __syncthreads();

    int tcol = (tid & 15) * 4;
    int trow = (tid >> 4) * 2;
    float acc[2][4] = {};
#pragma unroll
    for (int k = 0; k < NF; k++) {
        float4 w = *(const float4*)&Ws[k * NF + tcol];
        float a0 = Is[trow][k], a1 = Is[trow + 1][k];
        acc[0][0] += a0 * w.x; acc[0][1] += a0 * w.y;
        acc[0][2] += a0 * w.z; acc[0][3] += a0 * w.w;
        acc[1][0] += a1 * w.x; acc[1][1] += a1 * w.y;
        acc[1][2] += a1 * w.z; acc[1][3] += a1 * w.w;
    }
    float4 bb = *(const float4*)&b1[tcol];
#pragma unroll
    for (int rr = 0; rr < 2; rr++) {
        int g = row0 + trow + rr;
        float so = g_norm_out[g];
        float o0 = fmaxf(acc[rr][0] + bb.x, 0.f) * so;
        float o1 = fmaxf(acc[rr][1] + bb.y, 0.f) * so;
        float o2 = fmaxf(acc[rr][2] + bb.z, 0.f) * so;
        float o3 = fmaxf(acc[rr][3] + bb.w, 0.f) * so;
        g_h1[g * 32 + (tcol >> 1)]     = __floats2half2_rn(o0, o1);
        g_h1[g * 32 + (tcol >> 1) + 1] = __floats2half2_rn(o2, o3);
    }
}

// layer 2 + fused W3 transform: t3 = (relu(aggW2+b2)*norm_out) @ W3 (fp16) --
__global__ __launch_bounds__(256) void k_layer2(const float* __restrict__ W2,
                                                const float* __restrict__ b2,
                                                const float* __restrict__ W3) {
    __shared__ __align__(16) float Ws[NF * NF];
    __shared__ __align__(16) float W3s[NF * NC];
    __shared__ float Is[32][NF + 2];
    int tid = threadIdx.x;
    int row0 = blockIdx.x * 32;
    for (int i = tid; i < NF * NF; i += 256) Ws[i] = W2[i];
    for (int i = tid; i < NF * NC; i += 256) W3s[i] = W3[i];

    const __half* inh = (const __half*)g_h1;
    int wid = tid >> 5, lane = tid & 31;
    int sub = lane >> 3;
    int fc  = (lane & 7) * 8;
#pragma unroll
    for (int j = 0; j < 4; j++) {
        int nl = (wid << 2) + j;
        int node = row0 + nl;
        float acc[8];
        agg64_node(inh, g_row_ptr[node], g_row_ptr[node + 1], sub, fc, acc);
        if (lane < 8) {
            float ni = g_norm_in[node];
#pragma unroll
            for (int q = 0; q < 8; q++) Is[nl][fc + q] = acc[q] * ni;
        }
    }
    __syncthreads();

    int tcol = (tid & 15) * 4;
    int trow = (tid >> 4) * 2;
    float acc[2][4] = {};
#pragma unroll
    for (int k = 0; k < NF; k++) {
        float4 w = *(const float4*)&Ws[k * NF + tcol];
        float a0 = Is[trow][k], a1 = Is[trow + 1][k];
        acc[0][0] += a0 * w.x; acc[0][1] += a0 * w.y;
        acc[0][2] += a0 * w.z; acc[0][3] += a0 * w.w;
        acc[1][0] += a1 * w.x; acc[1][1] += a1 * w.y;
        acc[1][2] += a1 * w.z; acc[1][3] += a1 * w.w;
    }
    float4 bb = *(const float4*)&b2[tcol];
    float h2v[2][4];
#pragma unroll
    for (int rr = 0; rr < 2; rr++) {
        float so = g_norm_out[row0 + trow + rr];
        h2v[rr][0] = fmaxf(acc[rr][0] + bb.x, 0.f) * so;
        h2v[rr][1] = fmaxf(acc[rr][1] + bb.y, 0.f) * so;
        h2v[rr][2] = fmaxf(acc[rr][2] + bb.z, 0.f) * so;
        h2v[rr][3] = fmaxf(acc[rr][3] + bb.w, 0.f) * so;
    }
    __syncthreads();
#pragma unroll
    for (int rr = 0; rr < 2; rr++) {
        Is[trow + rr][tcol]     = h2v[rr][0];
        Is[trow + rr][tcol + 1] = h2v[rr][1];
        Is[trow + rr][tcol + 2] = h2v[rr][2];
        Is[trow + rr][tcol + 3] = h2v[rr][3];
    }
    __syncthreads();

    // phase 3: t3 = h2n @ W3  (32x32 tile, 1x4 per thread)
    int trow2 = tid >> 3;
    int tcol2 = (tid & 7) * 4;
    float a4[4] = {};
#pragma unroll
    for (int k = 0; k < NF; k++) {
        float h = Is[trow2][k];
        float4 w = *(const float4*)&W3s[k * NC + tcol2];
        a4[0] += h * w.x; a4[1] += h * w.y;
        a4[2] += h * w.z; a4[3] += h * w.w;
    }
    int g = row0 + trow2;
    g_t3[g * 16 + (tcol2 >> 1)]     = __floats2half2_rn(a4[0], a4[1]);
    g_t3[g * 16 + (tcol2 >> 1) + 1] = __floats2half2_rn(a4[2], a4[3]);
}

// ---------------- final: out = norm_in * Agg(t3) + b3 (+ deg re-zero) -----
// Warp per node; lane loads uint2 (4 halves): 8 lanes per 64B row, 4 edges/LDG.
__global__ void k_out(const float* __restrict__ b3, float* __restrict__ out) {
    int gt = blockIdx.x * blockDim.x + threadIdx.x;
    int w = gt >> 5, lane = gt & 31;
    int sub = lane >> 3;
    int fc  = (lane & 7) * 4;
    const __half* t3 = (const __half*)g_t3;
    int beg = g_row_ptr[w], end = g_row_ptr[w + 1];
    float acc[4] = {};
    for (int e = beg; e < end; e += 4) {
        int eid = e + sub;
        uint2 v = make_uint2(0u, 0u);
        if (eid < end) {
            int s = g_edge_src[eid];
            v = *(const uint2*)&t3[s * NC + fc];
        }
        float2 f0 = __half22float2(*(const __half2*)&v.x);
        float2 f1 = __half22float2(*(const __half2*)&v.y);
        acc[0] += f0.x; acc[1] += f0.y; acc[2] += f1.x; acc[3] += f1.y;
    }
#pragma unroll
    for (int q = 0; q < 4; q++) {
        acc[q] += __shfl_xor_sync(0xffffffffu, acc[q], 8);
        acc[q] += __shfl_xor_sync(0xffffffffu, acc[q], 16);
    }
    if (lane < 8) {
        float ni = g_norm_in[w];
        float4 bb = *(const float4*)&b3[fc];
        float4 o;
        o.x = acc[0] * ni + bb.x;
        o.y = acc[1] * ni + bb.y;
        o.z = acc[2] * ni + bb.z;
        o.w = acc[3] * ni + bb.w;
        *(float4*)&out[w * NC + fc] = o;
    }
    // restore zeroed degree state for next replay
    if (gt < NN) { g_deg_out[gt] = 0; g_deg_in[gt] = 0; }
}

// ---------------- launch -------------------------------------------------
extern "C" void kernel_launch(void* const* d_in, const int* in_sizes, int n_in,
                              void* d_out, int out_size) {
    const float* x   = (const float*)d_in[0];
    const int*   src = (const int*)d_in[1];
    const int*   dst = (const int*)d_in[2];
    const float* W1  = (const float*)d_in[3];
    const float* b1  = (const float*)d_in[4];
    const float* W2  = (const float*)d_in[5];
    const float* b2  = (const float*)d_in[6];
    const float* W3  = (const float*)d_in[7];
    const float* b3  = (const float*)d_in[8];
    float* out = (float*)d_out;

    const int NB_EDGE4 = (NE / 4 + 255) / 256;          // 1563
    const int NB_PRE   = (NN * (NF / 4) + 255) / 256;   // 6250
    const int NB_OUT   = NN * 32 / 256;                 // 12500

    k_hist<<<NB_EDGE4, 256>>>((const int4*)src, (const int4*)dst);
    k_scan1<<<SCAN_NB, SCAN_T>>>();
    k_scan2<<<1, 32>>>();
    k_scan3<<<SCAN_NB, SCAN_T>>>();
    k_scatter<<<NB_EDGE4, 256>>>((const int4*)src, (const int4*)dst);
    k_prescale<<<NB_PRE, 256>>>(x);
    k_layer1<<<NN / 32, 256>>>(W1, b1);
    k_layer2<<<NN / 32, 256>>>(W2, b2, W3);
    k_out<<<NB_OUT, 256>>>(b3, out);
}